// round 10
// baseline (speedup 1.0000x reference)
#include <cuda_runtime.h>

// Bloch-vector formulation (exact rewrite, verified R6):
//   z_q = s1*(rx*c2 + ry*s2) + rz*c1 ;  h_q = s1*(sx*c2 + sy*s2) + sz*c1
//   Z0 = a0 z_a + h_a z_b          Z1 = a1 z_b + h_b z_a z_c
//   Z2 = a2 z_c + h_c z_b z_d      Z3 = a3 z_d + h_d z_c
//
// 2 lines/thread, all 6 LDG.128 issued up-front (MLP=6: one DRAM round trip
// covers both lines), 256 CTAs of 512 threads (short launch ramp).

__device__ __forceinline__ float4 line_z(float4 F0, float4 F1, float4 F2,
                                         const float4* __restrict__ sc) {
    const float PI = 3.14159265358979323846f;
    float s1, c1, s2, c2;
    // qubit 0
    __sincosf(PI * F0.y, &s1, &c1);
    __sincosf(PI * F0.z, &s2, &c2);
    float4 r = sc[0], s = sc[4];
    float za = fmaf(s1, fmaf(r.y, s2, r.x * c2), r.z * c1);
    float ha = fmaf(s1, fmaf(s.y, s2, s.x * c2), s.z * c1);
    float aza = r.w * za;
    // qubit 1
    __sincosf(PI * F1.x, &s1, &c1);
    __sincosf(PI * F1.y, &s2, &c2);
    r = sc[1]; s = sc[5];
    float zb = fmaf(s1, fmaf(r.y, s2, r.x * c2), r.z * c1);
    float hb = fmaf(s1, fmaf(s.y, s2, s.x * c2), s.z * c1);
    float azb = r.w * zb;
    // qubit 2
    __sincosf(PI * F1.w, &s1, &c1);
    __sincosf(PI * F2.x, &s2, &c2);
    r = sc[2]; s = sc[6];
    float zc = fmaf(s1, fmaf(r.y, s2, r.x * c2), r.z * c1);
    float hc = fmaf(s1, fmaf(s.y, s2, s.x * c2), s.z * c1);
    float azc = r.w * zc;
    // qubit 3
    __sincosf(PI * F2.z, &s1, &c1);
    __sincosf(PI * F2.w, &s2, &c2);
    r = sc[3]; s = sc[7];
    float zd = fmaf(s1, fmaf(r.y, s2, r.x * c2), r.z * c1);
    float hd = fmaf(s1, fmaf(s.y, s2, s.x * c2), s.z * c1);
    float azd = r.w * zd;

    return make_float4(fmaf(ha, zb, aza),
                       fmaf(hb, za * zc, azb),
                       fmaf(hc, zb * zd, azc),
                       fmaf(hd, zc, azd));
}

__global__ __launch_bounds__(512)
void qcnn_kernel(const float* __restrict__ x, const float* __restrict__ w,
                 float* __restrict__ out) {
    // sc[q] = (r3x, r3y, r3z, a_q); sc[4+q] = (sx, sy, sz, 0)
    __shared__ float4 sc[8];

    int tid = threadIdx.x;
    int base = blockIdx.x * 1024;
    int t0 = base + tid;            // warp-coalesced line 0
    int t1 = base + 512 + tid;      // warp-coalesced line 1

    // w first (feeds the per-block precompute chain)
    float wv[6];
    if (tid < 4) {
#pragma unroll
        for (int k = 0; k < 3; k++) {
            wv[k]     = __ldg(w + tid * 3 + k);
            wv[3 + k] = __ldg(w + 12 + tid * 3 + k);
        }
    }
    // all 6 data loads up-front: one DRAM round trip for both lines,
    // overlapped with the constants precompute + barrier
    const float4* xb0 = (const float4*)(x + (size_t)t0 * 12);
    const float4* xb1 = (const float4*)(x + (size_t)t1 * 12);
    float4 E0 = __ldg(xb0 + 0), E1 = __ldg(xb0 + 1), E2 = __ldg(xb0 + 2);
    float4 G0 = __ldg(xb1 + 0), G1 = __ldg(xb1 + 1), G2 = __ldg(xb1 + 2);

    if (tid < 4) {
        int q = tid;
        // ---- layer-1 gate U1 = RZ(g)RY(b)RX(a): u00,u10 -> Bloch rotation ----
        float sa, ca, sb, cb, sg, cg;
        __sincosf(0.5f * wv[0], &sa, &ca);
        __sincosf(0.5f * wv[1], &sb, &cb);
        __sincosf(0.5f * wv[2], &sg, &cg);
        float m00r = cb * ca, m00i = sb * sa;
        float m10r = sb * ca, m10i = -cb * sa;
        float u00r = cg * m00r + sg * m00i, u00i = cg * m00i - sg * m00r;
        float u10r = cg * m10r - sg * m10i, u10i = cg * m10i + sg * m10r;
        float qt = u00r, qz = -u00i, qy = u10r, qx = -u10i;
        float r1x = 1.f - 2.f * (qy * qy + qz * qz);
        float r1y = 2.f * (qx * qy - qt * qz);
        float r1z = 2.f * (qx * qz + qt * qy);
        float r2x = 2.f * (qx * qy + qt * qz);
        float r2y = 1.f - 2.f * (qx * qx + qz * qz);
        float r2z = 2.f * (qy * qz - qt * qx);
        float r3x = 2.f * (qx * qz - qt * qy);
        float r3y = 2.f * (qy * qz + qt * qx);
        float r3z = 1.f - 2.f * (qx * qx + qy * qy);

        // ---- layer-2 gate U2 -> observable M = U2^dag Z U2 ----
        __sincosf(0.5f * wv[3], &sa, &ca);
        __sincosf(0.5f * wv[4], &sb, &cb);
        __sincosf(0.5f * wv[5], &sg, &cg);
        float n00r = cb * ca, n00i = sb * sa;
        float n01r = -sb * ca, n01i = -cb * sa;
        float n10r = sb * ca, n10i = -cb * sa;
        float n11r = cb * ca, n11i = -sb * sa;
        float v00r = cg * n00r + sg * n00i, v00i = cg * n00i - sg * n00r;
        float v01r = cg * n01r + sg * n01i, v01i = cg * n01i - sg * n01r;
        float v10r = cg * n10r - sg * n10i, v10i = cg * n10i + sg * n10r;
        float v11r = cg * n11r - sg * n11i, v11i = cg * n11i + sg * n11r;
        float ma = v00r * v00r + v00i * v00i - v10r * v10r - v10i * v10i;
        float mb = v00r * v01r + v00i * v01i - (v10r * v11r + v10i * v11i);
        float mc = v00r * v01i - v00i * v01r - (v10r * v11i - v10i * v11r);

        sc[q]     = make_float4(r3x, r3y, r3z, ma);
        sc[4 + q] = make_float4(mb * r1x - mc * r2x,
                                mb * r1y - mc * r2y,
                                mb * r1z - mc * r2z, 0.f);
    }
    __syncthreads();

    ((float4*)out)[t0] = line_z(E0, E1, E2, sc);
    ((float4*)out)[t1] = line_z(G0, G1, G2, sc);
}

extern "C" void kernel_launch(void* const* d_in, const int* in_sizes, int n_in,
                              void* d_out, int out_size) {
    const float* x = (const float*)d_in[0];   // [128, 2048, 4, 3] f32
    const float* w = (const float*)d_in[1];   // [2, 4, 3] f32
    float* out = (float*)d_out;               // [128, 2048, 4] f32

    int nlines = in_sizes[0] / 12;            // 262144
    int grid = nlines / 1024;                 // 256 CTAs x 512 thr x 2 lines
    qcnn_kernel<<<grid, 512>>>(x, w, out);
}